// round 9
// baseline (speedup 1.0000x reference)
#include <cuda_runtime.h>
#include <cuda_bf16.h>
#include <math.h>

// ---------------------------------------------------------------------------
// QuantumNeuralLayer: B=256, FEAT=64, Q=16, L=2, H_ENC=128, H_DEC=256
// psi[y] = sum_{c<4} w_c[yA] v_c[yB]; probs -> bf16 hi/lo (packed f32x2 math);
// decoder GEMM: mma.sync bf16 3-product compensation, ldmatrix + cp.async
// double buffer, in-kernel Wd1 fp32->bf16 hi/lo conversion (k_prep removed),
// deterministic split-K (32-way); fused reduce+decoder tail.
// ---------------------------------------------------------------------------

#define NB 256
typedef unsigned int uint;
typedef unsigned long long u64;

__device__ __align__(128) float2 g_a [NB][16][2];
__device__ __align__(128) float2 g_U2[NB][16][4];
__device__ __align__(128) float2 g_w [NB][4][256];
__device__ __align__(128) float2 g_v [NB][4][256];
__device__ __align__(128) __nv_bfloat16 g_Ahi[NB][65536];     // 32 MB, [m][k]
__device__ __align__(128) __nv_bfloat16 g_Alo[NB][65536];     // 32 MB
__device__ __align__(128) float g_part[32][NB][256];          // split-K partials (8 MB)

__device__ __forceinline__ float2 cmul(float2 a, float2 b) {
    return make_float2(a.x*b.x - a.y*b.y, a.x*b.y + a.y*b.x);
}
__device__ __forceinline__ float2 cadd(float2 a, float2 b) {
    return make_float2(a.x + b.x, a.y + b.y);
}

// packed f32x2 helpers (FFMA2 path is PTX-only)
__device__ __forceinline__ u64 pk2(float a, float b) {
    u64 r; asm("mov.b64 %0, {%1,%2};" : "=l"(r) : "f"(a), "f"(b)); return r;
}
__device__ __forceinline__ u64 fma2(u64 a, u64 b, u64 c) {
    u64 d; asm("fma.rn.f32x2 %0, %1, %2, %3;" : "=l"(d) : "l"(a), "l"(b), "l"(c)); return d;
}
__device__ __forceinline__ u64 mul2(u64 a, u64 b) {
    u64 d; asm("mul.rn.f32x2 %0, %1, %2;" : "=l"(d) : "l"(a), "l"(b)); return d;
}
__device__ __forceinline__ void upk2(u64 v, float& a, float& b) {
    asm("mov.b64 {%0,%1}, %2;" : "=f"(a), "=f"(b) : "l"(v));
}

// ---------------- Kernel 1: encoder MLP -> gate matrices -------------------
__global__ void k_encoder(const float* __restrict__ x,
                          const float* __restrict__ W1, const float* __restrict__ b1,
                          const float* __restrict__ W2, const float* __restrict__ b2,
                          const float* __restrict__ scaling)
{
    int b = blockIdx.x, tid = threadIdx.x;
    __shared__ float xs[64], hs[128], ang[96];

    if (tid < 64) xs[tid] = x[b*64 + tid];
    __syncthreads();

    if (tid < 128) {
        float s = b1[tid];
        #pragma unroll
        for (int i = 0; i < 64; i++) s += xs[i] * W1[i*128 + tid];
        hs[tid] = fmaxf(s, 0.f);
    }
    __syncthreads();

    if (tid < 96) {
        float s = b2[tid];
        #pragma unroll
        for (int j = 0; j < 128; j++) s += hs[j] * W2[j*96 + tid];
        int q = (tid/3) & 15;
        ang[tid] = tanhf(s) * scaling[q] * 3.14159265358979323846f;
    }
    __syncthreads();

    if (tid < 32) {
        int l = tid >> 4, q = tid & 15;
        float th  = ang[l*48 + q*3 + 0] * 0.5f;
        float ph  = ang[l*48 + q*3 + 1] * 0.5f;
        float lam = ang[l*48 + q*3 + 2] * 0.5f;
        float ct = cosf(th),  st = sinf(th);
        float cp = cosf(ph),  sp = sinf(ph);
        float cl = cosf(lam), sl = sinf(lam);
        float2 U00 = make_float2( cl*cp*ct + sl*sp*st,  cl*sp*st - sl*cp*ct);
        float2 U01 = make_float2(-cl*sp*ct - sl*cp*st, -cl*cp*st + sl*sp*ct);
        float2 U10 = make_float2( cl*sp*ct + sl*cp*st,  sl*sp*ct - cl*cp*st);
        float2 U11 = make_float2( cl*cp*ct + sl*sp*st,  sl*cp*ct - cl*sp*st);
        if (l == 0) {
            g_a[b][q][0] = U00;
            g_a[b][q][1] = U10;
        } else {
            g_U2[b][q][0] = U00; g_U2[b][q][1] = U01;
            g_U2[b][q][2] = U10; g_U2[b][q][3] = U11;
        }
    }
}

// ---------------- Kernel 2: rank-4 factors w_c, v_c ------------------------
#define BIT(t,i) (((t) >> (i)) & 1)

__global__ void k_wv()
{
    int b = blockIdx.x, tid = threadIdx.x;   // 256 threads
    __shared__ float2 sa[16][2];
    __shared__ float2 sU[16][4];
    __shared__ float2 vec[256];

    if (tid < 16) {
        sa[tid][0] = g_a[b][tid][0];
        sa[tid][1] = g_a[b][tid][1];
        #pragma unroll
        for (int e = 0; e < 4; e++) sU[tid][e] = g_U2[b][tid][e];
    }
    __syncthreads();

    const int qA[8] = {15, 6, 5, 4, 3, 2, 1, 0};

    for (int c = 0; c < 4; c++) {
        int c0 = c & 1, c9 = (c >> 1) & 1;

        // ---- w_c ----
        {
            int t = tid;
            float2 val = make_float2(0.f, 0.f);
            if ((t & 3) == c) {
                float2 f = sa[0][BIT(t,7) ^ BIT(t,0)];
                f = cmul(f, sa[1][BIT(t,7) ^ BIT(t,6) ^ BIT(t,0)]);
                f = cmul(f, sa[2][BIT(t,6) ^ BIT(t,5)]);
                f = cmul(f, sa[3][BIT(t,5) ^ BIT(t,4)]);
                f = cmul(f, sa[4][BIT(t,4) ^ BIT(t,3)]);
                f = cmul(f, sa[5][BIT(t,3) ^ BIT(t,2)]);
                f = cmul(f, sa[6][BIT(t,2) ^ BIT(t,1)]);
                val = f;
            }
            vec[t] = val;
        }
        __syncthreads();
        #pragma unroll
        for (int k = 0; k < 8; k++) {
            if (tid < 128) {
                int i0 = ((tid >> k) << (k+1)) | (tid & ((1 << k) - 1));
                int i1 = i0 | (1 << k);
                float2 x0 = vec[i0], x1 = vec[i1];
                const float2* G = sU[qA[k]];
                vec[i0] = cadd(cmul(G[0], x0), cmul(G[1], x1));
                vec[i1] = cadd(cmul(G[2], x0), cmul(G[3], x1));
            }
            __syncthreads();
        }
        g_w[b][c][tid] = vec[tid];
        __syncthreads();

        // ---- v_c ----
        {
            int t = tid;
            float2 f = sa[15][BIT(t,0) ^ c0];
            f = cmul(f, sa[7 ][c9 ^ BIT(t,7)]);
            f = cmul(f, sa[14][BIT(t,1) ^ BIT(t,0)]);
            f = cmul(f, sa[13][BIT(t,2) ^ BIT(t,1)]);
            f = cmul(f, sa[12][BIT(t,3) ^ BIT(t,2)]);
            f = cmul(f, sa[11][BIT(t,4) ^ BIT(t,3)]);
            f = cmul(f, sa[10][BIT(t,5) ^ BIT(t,4)]);
            f = cmul(f, sa[9 ][BIT(t,6) ^ BIT(t,5)]);
            f = cmul(f, sa[8 ][BIT(t,7) ^ BIT(t,6)]);
            vec[t] = f;
        }
        __syncthreads();
        #pragma unroll
        for (int k = 0; k < 8; k++) {
            if (tid < 128) {
                int i0 = ((tid >> k) << (k+1)) | (tid & ((1 << k) - 1));
                int i1 = i0 | (1 << k);
                float2 x0 = vec[i0], x1 = vec[i1];
                const float2* G = sU[14 - k];
                vec[i0] = cadd(cmul(G[0], x0), cmul(G[1], x1));
                vec[i1] = cadd(cmul(G[2], x0), cmul(G[3], x1));
            }
            __syncthreads();
        }
        g_v[b][c][tid] = vec[tid];
        __syncthreads();
    }
}

// ---------------- Kernel 3: probs -> bf16 hi/lo (packed f32x2) -------------
// grid (NB, 4), 256 threads. Thread owns yAhi = chunk*32 + (t>>3); the two
// psi values (bit0 = 0/1 of yA) live in the two lanes of packed f32x2
// accumulators. v broadcast-packed via mov.b64; 16 FMA2 + 2 packed sq / pair.
__global__ void k_probs()
{
    int b = blockIdx.x, chunk = blockIdx.y;
    int t = threadIdx.x;
    __shared__ float2 sv[4][256];   // 8 KB
    __shared__ float2 swv[4][64];   // 2 KB

    for (int i = t; i < 1024; i += 256) {
        int c = i >> 8, idx = i & 255;
        sv[c][idx] = g_v[b][c][idx];
    }
    for (int i = t; i < 256; i += 256) {
        int c = i >> 6, la = i & 63;
        swv[c][la] = g_w[b][c][chunk * 64 + la];
    }
    __syncthreads();

    int yh = t >> 3;          // local yAhi 0..31
    int j  = t & 7;
    u64 wx[4], wny[4], wy[4];
    #pragma unroll
    for (int c = 0; c < 4; c++) {
        float2 a = swv[c][yh * 2];
        float2 bb = swv[c][yh * 2 + 1];
        wx [c] = pk2(a.x, bb.x);
        wny[c] = pk2(-a.y, -bb.y);
        wy [c] = pk2(a.y, bb.y);
    }
    int ybase = (chunk * 32 + yh) << 9;

    #pragma unroll 8
    for (int i = 0; i < 32; i++) {
        int yB = j + 8 * i;
        u64 re = 0ull, im = 0ull;    // packed (e0, e1)
        #pragma unroll
        for (int c = 0; c < 4; c++) {
            float2 v = sv[c][yB];
            u64 vxx = pk2(v.x, v.x);
            u64 vyy = pk2(v.y, v.y);
            re = fma2(wx [c], vxx, re);
            re = fma2(wny[c], vyy, re);
            im = fma2(wx [c], vyy, im);
            im = fma2(wy [c], vxx, im);
        }
        u64 q = fma2(re, re, mul2(im, im));
        float q0, q1; upk2(q, q0, q1);
        __nv_bfloat162 h2 = __floats2bfloat162_rn(q0, q1);
        float l0 = q0 - __bfloat162float(__low2bfloat16(h2));
        float l1 = q1 - __bfloat162float(__high2bfloat16(h2));
        __nv_bfloat162 l2 = __floats2bfloat162_rn(l0, l1);
        int y0 = ybase + yB * 2;
        *(uint*)&g_Ahi[b][y0] = *reinterpret_cast<uint*>(&h2);
        *(uint*)&g_Alo[b][y0] = *reinterpret_cast<uint*>(&l2);
    }
}

// ---------------- Kernel 4: bf16 mma GEMM, in-kernel B conversion ----------
// probs[256,65536] @ Wd1[65536,256]; CTA 128x128, 8 warps (4M x 2N),
// warp tile 32x64; split-K 32-way (chunk 2048, 32 KSTEP=64 steps), 2 stages.
// B: cp.async fp32 Wd1 -> staging; convert to bf16 hi/lo [k][n] in smem.

#define AROW 72     // 64 + 8 pad (bf16)
#define BROW 136    // 128 + 8 pad (bf16)
#define A_ELEMS (128*AROW)          // 9216
#define B_ELEMS (64*BROW)           // 8704
#define OFF_AHI 0
#define OFF_ALO (A_ELEMS*2)                    // 18432
#define OFF_BHI (2*A_ELEMS*2)                  // 36864
#define OFF_BLO (OFF_BHI + B_ELEMS*2)          // 54272
#define OFF_BST (OFF_BLO + B_ELEMS*2)          // 71680
#define STAGE_BYTES (OFF_BST + 64*128*4)       // 104448
#define NSTEP 32

#define MMA16816(d, a, b0, b1)                                              \
    asm volatile("mma.sync.aligned.m16n8k16.row.col.f32.bf16.bf16.f32 "     \
        "{%0,%1,%2,%3}, {%4,%5,%6,%7}, {%8,%9}, {%0,%1,%2,%3};"             \
        : "+f"(d[0]), "+f"(d[1]), "+f"(d[2]), "+f"(d[3])                    \
        : "r"(a[0]), "r"(a[1]), "r"(a[2]), "r"(a[3]), "r"(b0), "r"(b1))

#define LDSM_X4(r, addr)                                                    \
    asm volatile("ldmatrix.sync.aligned.m8n8.x4.shared.b16 {%0,%1,%2,%3}, [%4];" \
        : "=r"(r[0]), "=r"(r[1]), "=r"(r[2]), "=r"(r[3]) : "r"(addr))

#define LDSM_X4_T(r, addr)                                                  \
    asm volatile("ldmatrix.sync.aligned.m8n8.x4.trans.shared.b16 {%0,%1,%2,%3}, [%4];" \
        : "=r"(r[0]), "=r"(r[1]), "=r"(r[2]), "=r"(r[3]) : "r"(addr))

#define CP16(dst, src)                                                      \
    asm volatile("cp.async.cg.shared.global [%0], [%1], 16;" :: "r"(dst), "l"(src))
#define CP_COMMIT() asm volatile("cp.async.commit_group;")
#define CP_WAIT1()  asm volatile("cp.async.wait_group 1;")

extern __shared__ __nv_bfloat16 smem_g[];

__device__ __forceinline__ void gemm_load_stage(uint sbase, int s, int m0c, int n0c,
                                                int k0, int t, const float* Wd1)
{
    uint st = sbase + s * STAGE_BYTES;
    uint aHi = st + OFF_AHI;
    uint aLo = st + OFF_ALO;
    uint bSt = st + OFF_BST;
    #pragma unroll
    for (int i = 0; i < 4; i++) {                 // A: 128 rows x 8 chunks
        int id = t + 256 * i;
        int row = id >> 3, c = id & 7;
        uint off = (uint)(row * AROW + c * 8) * 2;
        CP16(aHi + off, &g_Ahi[m0c + row][k0 + c * 8]);
        CP16(aLo + off, &g_Alo[m0c + row][k0 + c * 8]);
    }
    #pragma unroll
    for (int i = 0; i < 8; i++) {                 // B fp32: 64 rows x 32 chunks
        int id = t + 256 * i;
        int row = id >> 5, c = id & 31;
        uint off = (uint)(row * 512 + c * 16);
        CP16(bSt + off, &Wd1[(size_t)(k0 + row) * 256 + n0c + c * 4]);
    }
}

__global__ void __launch_bounds__(256, 1) k_gemm(const float* __restrict__ Wd1)
{
    uint sbase = (uint)__cvta_generic_to_shared(smem_g);

    int n0c = blockIdx.x * 128;
    int m0c = blockIdx.y * 128;
    int kz  = blockIdx.z;

    int t = threadIdx.x;
    int lane = t & 31, w = t >> 5;
    int wm = w & 3, wn = w >> 2;        // warp tile: rows [wm*32,+32), cols [wn*64,+64)

    float acc[2][8][4];
    #pragma unroll
    for (int i = 0; i < 2; i++)
        #pragma unroll
        for (int j = 0; j < 8; j++)
            #pragma unroll
            for (int e = 0; e < 4; e++) acc[i][j][e] = 0.f;

    // precomputed ldmatrix lane addresses (offsets within stage)
    int arow = wm * 32 + (lane & 15);
    int acol = ((lane >> 4) & 1) * 8;
    uint a_off = (uint)(arow * AROW + acol) * 2;
    int bkr = lane & 15;
    int bnc = wn * 64 + ((lane >> 4) & 1) * 8;
    uint b_off = (uint)(bkr * BROW + bnc) * 2;

    int kbase = kz * (NSTEP * 64);

    gemm_load_stage(sbase, 0, m0c, n0c, kbase, t, Wd1);
    CP_COMMIT();

    for (int s = 0; s < NSTEP; s++) {
        if (s + 1 < NSTEP)
            gemm_load_stage(sbase, (s + 1) & 1, m0c, n0c, kbase + (s + 1) * 64, t, Wd1);
        CP_COMMIT();
        CP_WAIT1();
        __syncthreads();

        char* stg = (char*)smem_g + (s & 1) * STAGE_BYTES;
        // ---- convert B fp32 -> bf16 hi/lo in smem ----
        {
            const float* bst = (const float*)(stg + OFF_BST);
            __nv_bfloat16* bhi = (__nv_bfloat16*)(stg + OFF_BHI);
            __nv_bfloat16* blo = (__nv_bfloat16*)(stg + OFF_BLO);
            #pragma unroll
            for (int i = 0; i < 8; i++) {
                int id = t + 256 * i;
                int row = id >> 5, c4 = (id & 31) * 4;
                float4 v = *(const float4*)&bst[row * 128 + c4];
                __nv_bfloat162 h0 = __floats2bfloat162_rn(v.x, v.y);
                __nv_bfloat162 h1 = __floats2bfloat162_rn(v.z, v.w);
                float lx = v.x - __bfloat162float(__low2bfloat16(h0));
                float ly = v.y - __bfloat162float(__high2bfloat16(h0));
                float lz = v.z - __bfloat162float(__low2bfloat16(h1));
                float lw = v.w - __bfloat162float(__high2bfloat16(h1));
                __nv_bfloat162 l0 = __floats2bfloat162_rn(lx, ly);
                __nv_bfloat162 l1 = __floats2bfloat162_rn(lz, lw);
                *(uint2*)&bhi[row * BROW + c4] =
                    make_uint2(*reinterpret_cast<uint*>(&h0), *reinterpret_cast<uint*>(&h1));
                *(uint2*)&blo[row * BROW + c4] =
                    make_uint2(*reinterpret_cast<uint*>(&l0), *reinterpret_cast<uint*>(&l1));
            }
        }
        __syncthreads();

        uint st = sbase + (uint)(s & 1) * STAGE_BYTES;
        uint aHi = st + OFF_AHI;
        uint aLo = st + OFF_ALO;
        uint bHi = st + OFF_BHI;
        uint bLo = st + OFF_BLO;

        #pragma unroll
        for (int ks = 0; ks < 4; ks++) {
            uint ah[2][4], al[2][4];
            #pragma unroll
            for (int i = 0; i < 2; i++) {
                uint ad = aHi + a_off + (uint)(i * 16 * AROW + ks * 16) * 2;
                LDSM_X4(ah[i], ad);
                uint ad2 = aLo + a_off + (uint)(i * 16 * AROW + ks * 16) * 2;
                LDSM_X4(al[i], ad2);
            }
            uint bh[4][4], bl[4][4];
            #pragma unroll
            for (int j2 = 0; j2 < 4; j2++) {
                uint bd = bHi + b_off + (uint)(ks * 16 * BROW + j2 * 16) * 2;
                LDSM_X4_T(bh[j2], bd);
                uint bd2 = bLo + b_off + (uint)(ks * 16 * BROW + j2 * 16) * 2;
                LDSM_X4_T(bl[j2], bd2);
            }
            #pragma unroll
            for (int i = 0; i < 2; i++)
                #pragma unroll
                for (int j2 = 0; j2 < 4; j2++)
                    #pragma unroll
                    for (int h = 0; h < 2; h++) {
                        int j = j2 * 2 + h;
                        MMA16816(acc[i][j], ah[i], bh[j2][2*h], bh[j2][2*h+1]);
                        MMA16816(acc[i][j], ah[i], bl[j2][2*h], bl[j2][2*h+1]);
                        MMA16816(acc[i][j], al[i], bh[j2][2*h], bh[j2][2*h+1]);
                    }
        }
        __syncthreads();
    }

    // epilogue: split-K partials
    int g = lane >> 2, tig = lane & 3;
    #pragma unroll
    for (int i = 0; i < 2; i++) {
        int r = m0c + wm * 32 + i * 16 + g;
        #pragma unroll
        for (int j = 0; j < 8; j++) {
            int col = n0c + wn * 64 + j * 8 + tig * 2;
            *(float2*)&g_part[kz][r    ][col] = make_float2(acc[i][j][0], acc[i][j][1]);
            *(float2*)&g_part[kz][r + 8][col] = make_float2(acc[i][j][2], acc[i][j][3]);
        }
    }
}

// ---------------- Kernel 5: fused reduce + decoder tail --------------------
__global__ void k_tail(const float* __restrict__ bd1,
                       const float* __restrict__ Wd2,
                       const float* __restrict__ bd2,
                       float* __restrict__ out)
{
    int b = blockIdx.x;           // 256 blocks, 256 threads
    int n = threadIdx.x;
    __shared__ float h[256];
    __shared__ float red[4][64];

    float s = 0.f;
    #pragma unroll
    for (int z = 0; z < 32; z++) s += g_part[z][b][n];
    h[n] = fmaxf(s + bd1[n], 0.f);
    __syncthreads();

    int n2 = n & 63, q = n >> 6;
    float s2 = 0.f;
    #pragma unroll 8
    for (int j = q * 64; j < q * 64 + 64; j++) s2 += h[j] * Wd2[j * 64 + n2];
    red[q][n2] = s2;
    __syncthreads();

    if (n < 64)
        out[b * 64 + n] = fmaxf(red[0][n] + red[1][n] + red[2][n] + red[3][n] + bd2[n], 0.f);
}

// ---------------------------------------------------------------------------
extern "C" void kernel_launch(void* const* d_in, const int* in_sizes, int n_in,
                              void* d_out, int out_size)
{
    const float* x       = (const float*)d_in[0];
    const float* W1      = (const float*)d_in[1];
    const float* b1      = (const float*)d_in[2];
    const float* W2      = (const float*)d_in[3];
    const float* b2      = (const float*)d_in[4];
    const float* scaling = (const float*)d_in[5];
    const float* Wd1     = (const float*)d_in[6];
    const float* bd1     = (const float*)d_in[7];
    const float* Wd2     = (const float*)d_in[8];
    const float* bd2     = (const float*)d_in[9];
    float* out = (float*)d_out;

    int smem_bytes = 2 * STAGE_BYTES;   // 208896
    cudaFuncSetAttribute(k_gemm, cudaFuncAttributeMaxDynamicSharedMemorySize, smem_bytes);

    k_encoder<<<NB, 128>>>(x, W1, b1, W2, b2, scaling);
    k_wv<<<NB, 256>>>();
    k_probs<<<dim3(NB, 4), 256>>>();
    k_gemm<<<dim3(2, 2, 32), 256, smem_bytes>>>(Wd1);
    k_tail<<<NB, 256>>>(bd1, Wd2, bd2, out);
}

// round 13
// speedup vs baseline: 1.3362x; 1.3362x over previous
#include <cuda_runtime.h>
#include <cuda_bf16.h>
#include <math.h>

// ---------------------------------------------------------------------------
// QuantumNeuralLayer: B=256, FEAT=64, Q=16, L=2, H_ENC=128, H_DEC=256
// psi[y] = sum_{c<4} w_c[yA] v_c[yB]; probs -> bf16 hi/lo (packed f32x2 math);
// decoder GEMM: mma.sync bf16 3-product compensation, ldmatrix + cp.async
// double buffer, separate Wd1 prep kernel, 16-warp CTA (32x32 warp tiles),
// deterministic split-K (32-way); fused reduce+decoder tail.
// ---------------------------------------------------------------------------

#define NB 256
typedef unsigned int uint;
typedef unsigned long long u64;

__device__ __align__(128) float2 g_a [NB][16][2];
__device__ __align__(128) float2 g_U2[NB][16][4];
__device__ __align__(128) float2 g_w [NB][4][256];
__device__ __align__(128) float2 g_v [NB][4][256];
__device__ __align__(128) __nv_bfloat16 g_Ahi[NB][65536];     // 32 MB, [m][k]
__device__ __align__(128) __nv_bfloat16 g_Alo[NB][65536];     // 32 MB
__device__ __align__(128) __nv_bfloat16 g_Bhi[65536][256];    // 32 MB, [k][n]
__device__ __align__(128) __nv_bfloat16 g_Blo[65536][256];    // 32 MB
__device__ __align__(128) float g_part[32][NB][256];          // split-K partials (8 MB)

__device__ __forceinline__ float2 cmul(float2 a, float2 b) {
    return make_float2(a.x*b.x - a.y*b.y, a.x*b.y + a.y*b.x);
}
__device__ __forceinline__ float2 cadd(float2 a, float2 b) {
    return make_float2(a.x + b.x, a.y + b.y);
}

// packed f32x2 helpers (FFMA2 path is PTX-only)
__device__ __forceinline__ u64 pk2(float a, float b) {
    u64 r; asm("mov.b64 %0, {%1,%2};" : "=l"(r) : "f"(a), "f"(b)); return r;
}
__device__ __forceinline__ u64 fma2(u64 a, u64 b, u64 c) {
    u64 d; asm("fma.rn.f32x2 %0, %1, %2, %3;" : "=l"(d) : "l"(a), "l"(b), "l"(c)); return d;
}
__device__ __forceinline__ u64 mul2(u64 a, u64 b) {
    u64 d; asm("mul.rn.f32x2 %0, %1, %2;" : "=l"(d) : "l"(a), "l"(b)); return d;
}
__device__ __forceinline__ void upk2(u64 v, float& a, float& b) {
    asm("mov.b64 {%0,%1}, %2;" : "=f"(a), "=f"(b) : "l"(v));
}

// ---------------- Kernel 1: encoder MLP -> gate matrices -------------------
__global__ void k_encoder(const float* __restrict__ x,
                          const float* __restrict__ W1, const float* __restrict__ b1,
                          const float* __restrict__ W2, const float* __restrict__ b2,
                          const float* __restrict__ scaling)
{
    int b = blockIdx.x, tid = threadIdx.x;
    __shared__ float xs[64], hs[128], ang[96];

    if (tid < 64) xs[tid] = x[b*64 + tid];
    __syncthreads();

    if (tid < 128) {
        float s = b1[tid];
        #pragma unroll
        for (int i = 0; i < 64; i++) s += xs[i] * W1[i*128 + tid];
        hs[tid] = fmaxf(s, 0.f);
    }
    __syncthreads();

    if (tid < 96) {
        float s = b2[tid];
        #pragma unroll
        for (int j = 0; j < 128; j++) s += hs[j] * W2[j*96 + tid];
        int q = (tid/3) & 15;
        ang[tid] = tanhf(s) * scaling[q] * 3.14159265358979323846f;
    }
    __syncthreads();

    if (tid < 32) {
        int l = tid >> 4, q = tid & 15;
        float th  = ang[l*48 + q*3 + 0] * 0.5f;
        float ph  = ang[l*48 + q*3 + 1] * 0.5f;
        float lam = ang[l*48 + q*3 + 2] * 0.5f;
        float ct = cosf(th),  st = sinf(th);
        float cp = cosf(ph),  sp = sinf(ph);
        float cl = cosf(lam), sl = sinf(lam);
        float2 U00 = make_float2( cl*cp*ct + sl*sp*st,  cl*sp*st - sl*cp*ct);
        float2 U01 = make_float2(-cl*sp*ct - sl*cp*st, -cl*cp*st + sl*sp*ct);
        float2 U10 = make_float2( cl*sp*ct + sl*cp*st,  sl*sp*ct - cl*cp*st);
        float2 U11 = make_float2( cl*cp*ct + sl*sp*st,  sl*cp*ct - cl*sp*st);
        if (l == 0) {
            g_a[b][q][0] = U00;
            g_a[b][q][1] = U10;
        } else {
            g_U2[b][q][0] = U00; g_U2[b][q][1] = U01;
            g_U2[b][q][2] = U10; g_U2[b][q][3] = U11;
        }
    }
}

// ---------------- Kernel 2: rank-4 factors w_c, v_c ------------------------
#define BIT(t,i) (((t) >> (i)) & 1)

__global__ void k_wv()
{
    int b = blockIdx.x, tid = threadIdx.x;   // 256 threads
    __shared__ float2 sa[16][2];
    __shared__ float2 sU[16][4];
    __shared__ float2 vec[256];

    if (tid < 16) {
        sa[tid][0] = g_a[b][tid][0];
        sa[tid][1] = g_a[b][tid][1];
        #pragma unroll
        for (int e = 0; e < 4; e++) sU[tid][e] = g_U2[b][tid][e];
    }
    __syncthreads();

    const int qA[8] = {15, 6, 5, 4, 3, 2, 1, 0};

    for (int c = 0; c < 4; c++) {
        int c0 = c & 1, c9 = (c >> 1) & 1;

        // ---- w_c ----
        {
            int t = tid;
            float2 val = make_float2(0.f, 0.f);
            if ((t & 3) == c) {
                float2 f = sa[0][BIT(t,7) ^ BIT(t,0)];
                f = cmul(f, sa[1][BIT(t,7) ^ BIT(t,6) ^ BIT(t,0)]);
                f = cmul(f, sa[2][BIT(t,6) ^ BIT(t,5)]);
                f = cmul(f, sa[3][BIT(t,5) ^ BIT(t,4)]);
                f = cmul(f, sa[4][BIT(t,4) ^ BIT(t,3)]);
                f = cmul(f, sa[5][BIT(t,3) ^ BIT(t,2)]);
                f = cmul(f, sa[6][BIT(t,2) ^ BIT(t,1)]);
                val = f;
            }
            vec[t] = val;
        }
        __syncthreads();
        #pragma unroll
        for (int k = 0; k < 8; k++) {
            if (tid < 128) {
                int i0 = ((tid >> k) << (k+1)) | (tid & ((1 << k) - 1));
                int i1 = i0 | (1 << k);
                float2 x0 = vec[i0], x1 = vec[i1];
                const float2* G = sU[qA[k]];
                vec[i0] = cadd(cmul(G[0], x0), cmul(G[1], x1));
                vec[i1] = cadd(cmul(G[2], x0), cmul(G[3], x1));
            }
            __syncthreads();
        }
        g_w[b][c][tid] = vec[tid];
        __syncthreads();

        // ---- v_c ----
        {
            int t = tid;
            float2 f = sa[15][BIT(t,0) ^ c0];
            f = cmul(f, sa[7 ][c9 ^ BIT(t,7)]);
            f = cmul(f, sa[14][BIT(t,1) ^ BIT(t,0)]);
            f = cmul(f, sa[13][BIT(t,2) ^ BIT(t,1)]);
            f = cmul(f, sa[12][BIT(t,3) ^ BIT(t,2)]);
            f = cmul(f, sa[11][BIT(t,4) ^ BIT(t,3)]);
            f = cmul(f, sa[10][BIT(t,5) ^ BIT(t,4)]);
            f = cmul(f, sa[9 ][BIT(t,6) ^ BIT(t,5)]);
            f = cmul(f, sa[8 ][BIT(t,7) ^ BIT(t,6)]);
            vec[t] = f;
        }
        __syncthreads();
        #pragma unroll
        for (int k = 0; k < 8; k++) {
            if (tid < 128) {
                int i0 = ((tid >> k) << (k+1)) | (tid & ((1 << k) - 1));
                int i1 = i0 | (1 << k);
                float2 x0 = vec[i0], x1 = vec[i1];
                const float2* G = sU[14 - k];
                vec[i0] = cadd(cmul(G[0], x0), cmul(G[1], x1));
                vec[i1] = cadd(cmul(G[2], x0), cmul(G[3], x1));
            }
            __syncthreads();
        }
        g_v[b][c][tid] = vec[tid];
        __syncthreads();
    }
}

// ---------------- Kernel 3: probs -> bf16 hi/lo (packed f32x2) -------------
__global__ void k_probs()
{
    int b = blockIdx.x, chunk = blockIdx.y;
    int t = threadIdx.x;
    __shared__ float2 sv[4][256];   // 8 KB
    __shared__ float2 swv[4][64];   // 2 KB

    for (int i = t; i < 1024; i += 256) {
        int c = i >> 8, idx = i & 255;
        sv[c][idx] = g_v[b][c][idx];
    }
    for (int i = t; i < 256; i += 256) {
        int c = i >> 6, la = i & 63;
        swv[c][la] = g_w[b][c][chunk * 64 + la];
    }
    __syncthreads();

    int yh = t >> 3;          // local yAhi 0..31
    int j  = t & 7;
    u64 wx[4], wny[4], wy[4];
    #pragma unroll
    for (int c = 0; c < 4; c++) {
        float2 a = swv[c][yh * 2];
        float2 bb = swv[c][yh * 2 + 1];
        wx [c] = pk2(a.x, bb.x);
        wny[c] = pk2(-a.y, -bb.y);
        wy [c] = pk2(a.y, bb.y);
    }
    int ybase = (chunk * 32 + yh) << 9;

    #pragma unroll 8
    for (int i = 0; i < 32; i++) {
        int yB = j + 8 * i;
        u64 re = 0ull, im = 0ull;    // packed (e0, e1)
        #pragma unroll
        for (int c = 0; c < 4; c++) {
            float2 v = sv[c][yB];
            u64 vxx = pk2(v.x, v.x);
            u64 vyy = pk2(v.y, v.y);
            re = fma2(wx [c], vxx, re);
            re = fma2(wny[c], vyy, re);
            im = fma2(wx [c], vyy, im);
            im = fma2(wy [c], vxx, im);
        }
        u64 q = fma2(re, re, mul2(im, im));
        float q0, q1; upk2(q, q0, q1);
        __nv_bfloat162 h2 = __floats2bfloat162_rn(q0, q1);
        float l0 = q0 - __bfloat162float(__low2bfloat16(h2));
        float l1 = q1 - __bfloat162float(__high2bfloat16(h2));
        __nv_bfloat162 l2 = __floats2bfloat162_rn(l0, l1);
        int y0 = ybase + yB * 2;
        *(uint*)&g_Ahi[b][y0] = *reinterpret_cast<uint*>(&h2);
        *(uint*)&g_Alo[b][y0] = *reinterpret_cast<uint*>(&l2);
    }
}

// ---------------- Kernel 3b: Wd1 -> bf16 hi/lo [k][n] ----------------------
__global__ void k_prep(const float* __restrict__ Wd1)
{
    size_t i = ((size_t)blockIdx.x * 256 + threadIdx.x) * 4;   // 16384 blocks
    float4 v = *(const float4*)&Wd1[i];
    __nv_bfloat162 h0 = __floats2bfloat162_rn(v.x, v.y);
    __nv_bfloat162 h1 = __floats2bfloat162_rn(v.z, v.w);
    float lx = v.x - __bfloat162float(__low2bfloat16(h0));
    float ly = v.y - __bfloat162float(__high2bfloat16(h0));
    float lz = v.z - __bfloat162float(__low2bfloat16(h1));
    float lw = v.w - __bfloat162float(__high2bfloat16(h1));
    __nv_bfloat162 l0 = __floats2bfloat162_rn(lx, ly);
    __nv_bfloat162 l1 = __floats2bfloat162_rn(lz, lw);
    uint2 hw = make_uint2(*reinterpret_cast<uint*>(&h0), *reinterpret_cast<uint*>(&h1));
    uint2 lw2 = make_uint2(*reinterpret_cast<uint*>(&l0), *reinterpret_cast<uint*>(&l1));
    *(uint2*)((__nv_bfloat16*)g_Bhi + i) = hw;
    *(uint2*)((__nv_bfloat16*)g_Blo + i) = lw2;
}

// ---------------- Kernel 4: bf16 mma GEMM, 16 warps ------------------------
// probs[256,65536] @ Wd1[65536,256]; CTA 128x128, 16 warps (4M x 4N) of
// 32x32 warp tiles; split-K 32-way (chunk 2048, 32 KSTEP=64 steps), 2 stages.

#define AROW 72     // 64 + 8 pad (bf16)
#define BROW 136    // 128 + 8 pad (bf16)
#define A_ELEMS (128*AROW)          // 9216
#define B_ELEMS (64*BROW)           // 8704
#define STAGE_ELEMS (2*A_ELEMS + 2*B_ELEMS)   // 35840
#define STAGE_BYTES (STAGE_ELEMS*2)           // 71680
#define NSTEP 32

#define MMA16816(d, a, b0, b1)                                              \
    asm volatile("mma.sync.aligned.m16n8k16.row.col.f32.bf16.bf16.f32 "     \
        "{%0,%1,%2,%3}, {%4,%5,%6,%7}, {%8,%9}, {%0,%1,%2,%3};"             \
        : "+f"(d[0]), "+f"(d[1]), "+f"(d[2]), "+f"(d[3])                    \
        : "r"(a[0]), "r"(a[1]), "r"(a[2]), "r"(a[3]), "r"(b0), "r"(b1))

#define LDSM_X4(r, addr)                                                    \
    asm volatile("ldmatrix.sync.aligned.m8n8.x4.shared.b16 {%0,%1,%2,%3}, [%4];" \
        : "=r"(r[0]), "=r"(r[1]), "=r"(r[2]), "=r"(r[3]) : "r"(addr))

#define LDSM_X4_T(r, addr)                                                  \
    asm volatile("ldmatrix.sync.aligned.m8n8.x4.trans.shared.b16 {%0,%1,%2,%3}, [%4];" \
        : "=r"(r[0]), "=r"(r[1]), "=r"(r[2]), "=r"(r[3]) : "r"(addr))

#define CP16(dst, src)                                                      \
    asm volatile("cp.async.cg.shared.global [%0], [%1], 16;" :: "r"(dst), "l"(src))
#define CP_COMMIT() asm volatile("cp.async.commit_group;")
#define CP_WAIT1()  asm volatile("cp.async.wait_group 1;")

extern __shared__ __nv_bfloat16 smem_g[];

__device__ __forceinline__ void gemm_load_stage(uint sbase, int s, int m0c, int n0c,
                                                int k0, int t)
{
    uint aHi = sbase + s * STAGE_BYTES;
    uint aLo = aHi + A_ELEMS * 2;
    uint bHi = aLo + A_ELEMS * 2;
    uint bLo = bHi + B_ELEMS * 2;
    #pragma unroll
    for (int i = 0; i < 2; i++) {                 // A: 128 rows x 8 chunks (1024 cp)
        int id = t + 512 * i;
        int row = id >> 3, c = id & 7;
        uint off = (uint)(row * AROW + c * 8) * 2;
        CP16(aHi + off, &g_Ahi[m0c + row][k0 + c * 8]);
        CP16(aLo + off, &g_Alo[m0c + row][k0 + c * 8]);
    }
    #pragma unroll
    for (int i = 0; i < 2; i++) {                 // B: 64 rows x 16 chunks (1024 cp)
        int id = t + 512 * i;
        int row = id >> 4, c = id & 15;
        uint off = (uint)(row * BROW + c * 8) * 2;
        CP16(bHi + off, &g_Bhi[k0 + row][n0c + c * 8]);
        CP16(bLo + off, &g_Blo[k0 + row][n0c + c * 8]);
    }
}

__global__ void __launch_bounds__(512, 1) k_gemm()
{
    uint sbase = (uint)__cvta_generic_to_shared(smem_g);

    int n0c = blockIdx.x * 128;
    int m0c = blockIdx.y * 128;
    int kz  = blockIdx.z;

    int t = threadIdx.x;               // 512 threads, 16 warps
    int lane = t & 31, w = t >> 5;
    int wm = w & 3, wn = w >> 2;       // warp tile: rows [wm*32,+32), cols [wn*32,+32)

    float acc[2][4][4];
    #pragma unroll
    for (int i = 0; i < 2; i++)
        #pragma unroll
        for (int j = 0; j < 4; j++)
            #pragma unroll
            for (int e = 0; e < 4; e++) acc[i][j][e] = 0.f;

    // ldmatrix lane addresses (offsets within stage)
    int arow = wm * 32 + (lane & 15);
    int acol = ((lane >> 4) & 1) * 8;
    uint a_off = (uint)(arow * AROW + acol) * 2;
    int bkr = lane & 15;
    int bnc = wn * 32 + ((lane >> 4) & 1) * 8;
    uint b_off = (uint)(bkr * BROW + bnc) * 2;

    int kbase = kz * (NSTEP * 64);

    gemm_load_stage(sbase, 0, m0c, n0c, kbase, t);
    CP_COMMIT();

    for (int s = 0; s < NSTEP; s++) {
        if (s + 1 < NSTEP)
            gemm_load_stage(sbase, (s + 1) & 1, m0c, n0c, kbase + (s + 1) * 64, t);
        CP_COMMIT();
        CP_WAIT1();
        __syncthreads();

        uint aHi = sbase + (uint)(s & 1) * STAGE_BYTES;
        uint aLo = aHi + A_ELEMS * 2;
        uint bHi = aLo + A_ELEMS * 2;
        uint bLo = bHi + B_ELEMS * 2;

        #pragma unroll
        for (int ks = 0; ks < 4; ks++) {
            uint ah[2][4], al[2][4];
            #pragma unroll
            for (int i = 0; i < 2; i++) {
                LDSM_X4(ah[i], aHi + a_off + (uint)(i * 16 * AROW + ks * 16) * 2);
                LDSM_X4(al[i], aLo + a_off + (uint)(i * 16 * AROW + ks * 16) * 2);
            }
            uint bh[2][4], bl[2][4];
            #pragma unroll
            for (int j2 = 0; j2 < 2; j2++) {
                LDSM_X4_T(bh[j2], bHi + b_off + (uint)(ks * 16 * BROW + j2 * 16) * 2);
                LDSM_X4_T(bl[j2], bLo + b_off + (uint)(ks * 16 * BROW + j2 * 16) * 2);
            }
            #pragma unroll
            for (int i = 0; i < 2; i++)
                #pragma unroll
                for (int j2 = 0; j2 < 2; j2++)
                    #pragma unroll
                    for (int h = 0; h < 2; h++) {
                        int j = j2 * 2 + h;
                        MMA16816(acc[i][j], ah[i], bh[j2][2*h], bh[j2][2*h+1]);
                        MMA16816(acc[i][j], ah[i], bl[j2][2*h], bl[j2][2*h+1]);
                        MMA16816(acc[i][j], al[i], bh[j2][2*h], bh[j2][2*h+1]);
                    }
        }
        __syncthreads();
    }

    // epilogue: split-K partials
    int g = lane >> 2, tig = lane & 3;
    #pragma unroll
    for (int i = 0; i < 2; i++) {
        int r = m0c + wm * 32 + i * 16 + g;
        #pragma unroll
        for (int j = 0; j < 4; j++) {
            int col = n0c + wn * 32 + j * 8 + tig * 2;
            *(float2*)&g_part[kz][r    ][col] = make_float2(acc[i][j][0], acc[i][j][1]);
            *(float2*)&g_part[kz][r + 8][col] = make_float2(acc[i][j][2], acc[i][j][3]);
        }
    }
}

// ---------------- Kernel 5: fused reduce + decoder tail --------------------
__global__ void k_tail(const float* __restrict__ bd1,
                       const float* __restrict__ Wd2,
                       const float* __restrict__ bd2,
                       float* __restrict__ out)
{
    int b = blockIdx.x;           // 256 blocks, 256 threads
    int n = threadIdx.x;
    __shared__ float h[256];
    __shared__ float red[4][64];

    float s = 0.f;
    #pragma unroll
    for (int z = 0; z < 32; z++) s += g_part[z][b][n];
    h[n] = fmaxf(s + bd1[n], 0.f);
    __syncthreads();

    int n2 = n & 63, q = n >> 6;
    float s2 = 0.f;
    #pragma unroll 8
    for (int j = q * 64; j < q * 64 + 64; j++) s2 += h[j] * Wd2[j * 64 + n2];
    red[q][n2] = s2;
    __syncthreads();

    if (n < 64)
        out[b * 64 + n] = fmaxf(red[0][n] + red[1][n] + red[2][n] + red[3][n] + bd2[n], 0.f);
}

// ---------------------------------------------------------------------------
extern "C" void kernel_launch(void* const* d_in, const int* in_sizes, int n_in,
                              void* d_out, int out_size)
{
    const float* x       = (const float*)d_in[0];
    const float* W1      = (const float*)d_in[1];
    const float* b1      = (const float*)d_in[2];
    const float* W2      = (const float*)d_in[3];
    const float* b2      = (const float*)d_in[4];
    const float* scaling = (const float*)d_in[5];
    const float* Wd1     = (const float*)d_in[6];
    const float* bd1     = (const float*)d_in[7];
    const float* Wd2     = (const float*)d_in[8];
    const float* bd2     = (const float*)d_in[9];
    float* out = (float*)d_out;

    int smem_bytes = 2 * STAGE_BYTES;   // 143360
    cudaFuncSetAttribute(k_gemm, cudaFuncAttributeMaxDynamicSharedMemorySize, smem_bytes);

    k_prep<<<16384, 256>>>(Wd1);
    k_encoder<<<NB, 128>>>(x, W1, b1, W2, b2, scaling);
    k_wv<<<NB, 256>>>();
    k_probs<<<dim3(NB, 4), 256>>>();
    k_gemm<<<dim3(2, 2, 32), 512, smem_bytes>>>();
    k_tail<<<NB, 256>>>(bd1, Wd2, bd2, out);
}

// round 15
// speedup vs baseline: 1.3791x; 1.0321x over previous
#include <cuda_runtime.h>
#include <cuda_bf16.h>
#include <math.h>

// ---------------------------------------------------------------------------
// QuantumNeuralLayer: B=256, FEAT=64, Q=16, L=2, H_ENC=128, H_DEC=256
// psi[y] = sum_{c<4} w_c[yA] v_c[yB]; probs -> bf16 hi/lo (packed f32x2);
// decoder GEMM: mma.sync bf16 3-product compensation, ldmatrix + 3-stage
// cp.async pipeline (tcgen05 unavailable: harness PTX target is compute_103),
// separate Wd1 prep, deterministic split-K (32-way); fused reduce+tail.
// ---------------------------------------------------------------------------

#define NB 256
typedef unsigned int uint;
typedef unsigned long long u64;

__device__ __align__(128) float2 g_a [NB][16][2];
__device__ __align__(128) float2 g_U2[NB][16][4];
__device__ __align__(128) float2 g_w [NB][4][256];
__device__ __align__(128) float2 g_v [NB][4][256];
__device__ __align__(128) __nv_bfloat16 g_Ahi[NB][65536];     // 32 MB, [m][k]
__device__ __align__(128) __nv_bfloat16 g_Alo[NB][65536];     // 32 MB
__device__ __align__(128) __nv_bfloat16 g_Bhi[65536][256];    // 32 MB, [k][n]
__device__ __align__(128) __nv_bfloat16 g_Blo[65536][256];    // 32 MB
__device__ __align__(128) float g_part[32][NB][256];          // split-K partials (8 MB)

__device__ __forceinline__ float2 cmul(float2 a, float2 b) {
    return make_float2(a.x*b.x - a.y*b.y, a.x*b.y + a.y*b.x);
}
__device__ __forceinline__ float2 cadd(float2 a, float2 b) {
    return make_float2(a.x + b.x, a.y + b.y);
}

// packed f32x2 helpers (FFMA2 path is PTX-only)
__device__ __forceinline__ u64 pk2(float a, float b) {
    u64 r; asm("mov.b64 %0, {%1,%2};" : "=l"(r) : "f"(a), "f"(b)); return r;
}
__device__ __forceinline__ u64 fma2(u64 a, u64 b, u64 c) {
    u64 d; asm("fma.rn.f32x2 %0, %1, %2, %3;" : "=l"(d) : "l"(a), "l"(b), "l"(c)); return d;
}
__device__ __forceinline__ u64 mul2(u64 a, u64 b) {
    u64 d; asm("mul.rn.f32x2 %0, %1, %2;" : "=l"(d) : "l"(a), "l"(b)); return d;
}
__device__ __forceinline__ void upk2(u64 v, float& a, float& b) {
    asm("mov.b64 {%0,%1}, %2;" : "=f"(a), "=f"(b) : "l"(v));
}

// ---------------- Kernel 1: encoder MLP -> gate matrices -------------------
__global__ void k_encoder(const float* __restrict__ x,
                          const float* __restrict__ W1, const float* __restrict__ b1,
                          const float* __restrict__ W2, const float* __restrict__ b2,
                          const float* __restrict__ scaling)
{
    int b = blockIdx.x, tid = threadIdx.x;
    __shared__ float xs[64], hs[128], ang[96];

    if (tid < 64) xs[tid] = x[b*64 + tid];
    __syncthreads();

    if (tid < 128) {
        float s = b1[tid];
        #pragma unroll
        for (int i = 0; i < 64; i++) s += xs[i] * W1[i*128 + tid];
        hs[tid] = fmaxf(s, 0.f);
    }
    __syncthreads();

    if (tid < 96) {
        float s = b2[tid];
        #pragma unroll
        for (int j = 0; j < 128; j++) s += hs[j] * W2[j*96 + tid];
        int q = (tid/3) & 15;
        ang[tid] = tanhf(s) * scaling[q] * 3.14159265358979323846f;
    }
    __syncthreads();

    if (tid < 32) {
        int l = tid >> 4, q = tid & 15;
        float th  = ang[l*48 + q*3 + 0] * 0.5f;
        float ph  = ang[l*48 + q*3 + 1] * 0.5f;
        float lam = ang[l*48 + q*3 + 2] * 0.5f;
        float ct = cosf(th),  st = sinf(th);
        float cp = cosf(ph),  sp = sinf(ph);
        float cl = cosf(lam), sl = sinf(lam);
        float2 U00 = make_float2( cl*cp*ct + sl*sp*st,  cl*sp*st - sl*cp*ct);
        float2 U01 = make_float2(-cl*sp*ct - sl*cp*st, -cl*cp*st + sl*sp*ct);
        float2 U10 = make_float2( cl*sp*ct + sl*cp*st,  sl*sp*ct - cl*cp*st);
        float2 U11 = make_float2( cl*cp*ct + sl*sp*st,  sl*cp*ct - cl*sp*st);
        if (l == 0) {
            g_a[b][q][0] = U00;
            g_a[b][q][1] = U10;
        } else {
            g_U2[b][q][0] = U00; g_U2[b][q][1] = U01;
            g_U2[b][q][2] = U10; g_U2[b][q][3] = U11;
        }
    }
}

// ---------------- Kernel 2: rank-4 factors w_c, v_c ------------------------
#define BIT(t,i) (((t) >> (i)) & 1)

__global__ void k_wv()
{
    int b = blockIdx.x, tid = threadIdx.x;   // 256 threads
    __shared__ float2 sa[16][2];
    __shared__ float2 sU[16][4];
    __shared__ float2 vec[256];

    if (tid < 16) {
        sa[tid][0] = g_a[b][tid][0];
        sa[tid][1] = g_a[b][tid][1];
        #pragma unroll
        for (int e = 0; e < 4; e++) sU[tid][e] = g_U2[b][tid][e];
    }
    __syncthreads();

    const int qA[8] = {15, 6, 5, 4, 3, 2, 1, 0};

    for (int c = 0; c < 4; c++) {
        int c0 = c & 1, c9 = (c >> 1) & 1;

        // ---- w_c ----
        {
            int t = tid;
            float2 val = make_float2(0.f, 0.f);
            if ((t & 3) == c) {
                float2 f = sa[0][BIT(t,7) ^ BIT(t,0)];
                f = cmul(f, sa[1][BIT(t,7) ^ BIT(t,6) ^ BIT(t,0)]);
                f = cmul(f, sa[2][BIT(t,6) ^ BIT(t,5)]);
                f = cmul(f, sa[3][BIT(t,5) ^ BIT(t,4)]);
                f = cmul(f, sa[4][BIT(t,4) ^ BIT(t,3)]);
                f = cmul(f, sa[5][BIT(t,3) ^ BIT(t,2)]);
                f = cmul(f, sa[6][BIT(t,2) ^ BIT(t,1)]);
                val = f;
            }
            vec[t] = val;
        }
        __syncthreads();
        #pragma unroll
        for (int k = 0; k < 8; k++) {
            if (tid < 128) {
                int i0 = ((tid >> k) << (k+1)) | (tid & ((1 << k) - 1));
                int i1 = i0 | (1 << k);
                float2 x0 = vec[i0], x1 = vec[i1];
                const float2* G = sU[qA[k]];
                vec[i0] = cadd(cmul(G[0], x0), cmul(G[1], x1));
                vec[i1] = cadd(cmul(G[2], x0), cmul(G[3], x1));
            }
            __syncthreads();
        }
        g_w[b][c][tid] = vec[tid];
        __syncthreads();

        // ---- v_c ----
        {
            int t = tid;
            float2 f = sa[15][BIT(t,0) ^ c0];
            f = cmul(f, sa[7 ][c9 ^ BIT(t,7)]);
            f = cmul(f, sa[14][BIT(t,1) ^ BIT(t,0)]);
            f = cmul(f, sa[13][BIT(t,2) ^ BIT(t,1)]);
            f = cmul(f, sa[12][BIT(t,3) ^ BIT(t,2)]);
            f = cmul(f, sa[11][BIT(t,4) ^ BIT(t,3)]);
            f = cmul(f, sa[10][BIT(t,5) ^ BIT(t,4)]);
            f = cmul(f, sa[9 ][BIT(t,6) ^ BIT(t,5)]);
            f = cmul(f, sa[8 ][BIT(t,7) ^ BIT(t,6)]);
            vec[t] = f;
        }
        __syncthreads();
        #pragma unroll
        for (int k = 0; k < 8; k++) {
            if (tid < 128) {
                int i0 = ((tid >> k) << (k+1)) | (tid & ((1 << k) - 1));
                int i1 = i0 | (1 << k);
                float2 x0 = vec[i0], x1 = vec[i1];
                const float2* G = sU[14 - k];
                vec[i0] = cadd(cmul(G[0], x0), cmul(G[1], x1));
                vec[i1] = cadd(cmul(G[2], x0), cmul(G[3], x1));
            }
            __syncthreads();
        }
        g_v[b][c][tid] = vec[tid];
        __syncthreads();
    }
}

// ---------------- Kernel 3: probs -> bf16 hi/lo (packed f32x2) -------------
__global__ void k_probs()
{
    int b = blockIdx.x, chunk = blockIdx.y;
    int t = threadIdx.x;
    __shared__ float2 sv[4][256];   // 8 KB
    __shared__ float2 swv[4][64];   // 2 KB

    for (int i = t; i < 1024; i += 256) {
        int c = i >> 8, idx = i & 255;
        sv[c][idx] = g_v[b][c][idx];
    }
    for (int i = t; i < 256; i += 256) {
        int c = i >> 6, la = i & 63;
        swv[c][la] = g_w[b][c][chunk * 64 + la];
    }
    __syncthreads();

    int yh = t >> 3;          // local yAhi 0..31
    int j  = t & 7;
    u64 wx[4], wny[4], wy[4];
    #pragma unroll
    for (int c = 0; c < 4; c++) {
        float2 a = swv[c][yh * 2];
        float2 bb = swv[c][yh * 2 + 1];
        wx [c] = pk2(a.x, bb.x);
        wny[c] = pk2(-a.y, -bb.y);
        wy [c] = pk2(a.y, bb.y);
    }
    int ybase = (chunk * 32 + yh) << 9;

    #pragma unroll 8
    for (int i = 0; i < 32; i++) {
        int yB = j + 8 * i;
        u64 re = 0ull, im = 0ull;    // packed (e0, e1)
        #pragma unroll
        for (int c = 0; c < 4; c++) {
            float2 v = sv[c][yB];
            u64 vxx = pk2(v.x, v.x);
            u64 vyy = pk2(v.y, v.y);
            re = fma2(wx [c], vxx, re);
            re = fma2(wny[c], vyy, re);
            im = fma2(wx [c], vyy, im);
            im = fma2(wy [c], vxx, im);
        }
        u64 q = fma2(re, re, mul2(im, im));
        float q0, q1; upk2(q, q0, q1);
        __nv_bfloat162 h2 = __floats2bfloat162_rn(q0, q1);
        float l0 = q0 - __bfloat162float(__low2bfloat16(h2));
        float l1 = q1 - __bfloat162float(__high2bfloat16(h2));
        __nv_bfloat162 l2 = __floats2bfloat162_rn(l0, l1);
        int y0 = ybase + yB * 2;
        *(uint*)&g_Ahi[b][y0] = *reinterpret_cast<uint*>(&h2);
        *(uint*)&g_Alo[b][y0] = *reinterpret_cast<uint*>(&l2);
    }
}

// ---------------- Kernel 3b: Wd1 -> bf16 hi/lo [k][n] ----------------------
__global__ void k_prep(const float* __restrict__ Wd1)
{
    size_t i = ((size_t)blockIdx.x * 256 + threadIdx.x) * 4;   // 16384 blocks
    float4 v = *(const float4*)&Wd1[i];
    __nv_bfloat162 h0 = __floats2bfloat162_rn(v.x, v.y);
    __nv_bfloat162 h1 = __floats2bfloat162_rn(v.z, v.w);
    float lx = v.x - __bfloat162float(__low2bfloat16(h0));
    float ly = v.y - __bfloat162float(__high2bfloat16(h0));
    float lz = v.z - __bfloat162float(__low2bfloat16(h1));
    float lw = v.w - __bfloat162float(__high2bfloat16(h1));
    __nv_bfloat162 l0 = __floats2bfloat162_rn(lx, ly);
    __nv_bfloat162 l1 = __floats2bfloat162_rn(lz, lw);
    uint2 hw = make_uint2(*reinterpret_cast<uint*>(&h0), *reinterpret_cast<uint*>(&h1));
    uint2 lw2 = make_uint2(*reinterpret_cast<uint*>(&l0), *reinterpret_cast<uint*>(&l1));
    *(uint2*)((__nv_bfloat16*)g_Bhi + i) = hw;
    *(uint2*)((__nv_bfloat16*)g_Blo + i) = lw2;
}

// ---------------- Kernel 4: bf16 mma GEMM, 3-stage pipeline ----------------
// probs[256,65536] @ Wd1[65536,256]; CTA 128x128, 8 warps (4M x 2N),
// warp tile 32x64; split-K 32-way (chunk 2048, 32 KSTEP=64 steps), 3 stages.

#define AROW 72     // 64 + 8 pad (bf16)
#define BROW 136    // 128 + 8 pad (bf16)
#define A_ELEMS (128*AROW)          // 9216
#define B_ELEMS (64*BROW)           // 8704
#define STAGE_ELEMS (2*A_ELEMS + 2*B_ELEMS)   // 35840
#define STAGE_BYTES (STAGE_ELEMS*2)           // 71680
#define NSTAGE 3
#define NSTEP 32

#define MMA16816(d, a, b0, b1)                                              \
    asm volatile("mma.sync.aligned.m16n8k16.row.col.f32.bf16.bf16.f32 "     \
        "{%0,%1,%2,%3}, {%4,%5,%6,%7}, {%8,%9}, {%0,%1,%2,%3};"             \
        : "+f"(d[0]), "+f"(d[1]), "+f"(d[2]), "+f"(d[3])                    \
        : "r"(a[0]), "r"(a[1]), "r"(a[2]), "r"(a[3]), "r"(b0), "r"(b1))

#define LDSM_X4(r, addr)                                                    \
    asm volatile("ldmatrix.sync.aligned.m8n8.x4.shared.b16 {%0,%1,%2,%3}, [%4];" \
        : "=r"(r[0]), "=r"(r[1]), "=r"(r[2]), "=r"(r[3]) : "r"(addr))

#define LDSM_X4_T(r, addr)                                                  \
    asm volatile("ldmatrix.sync.aligned.m8n8.x4.trans.shared.b16 {%0,%1,%2,%3}, [%4];" \
        : "=r"(r[0]), "=r"(r[1]), "=r"(r[2]), "=r"(r[3]) : "r"(addr))

#define CP16(dst, src)                                                      \
    asm volatile("cp.async.cg.shared.global [%0], [%1], 16;" :: "r"(dst), "l"(src))
#define CP_COMMIT() asm volatile("cp.async.commit_group;")
#define CP_WAIT_G1() asm volatile("cp.async.wait_group 1;")

extern __shared__ __nv_bfloat16 smem_g[];

__device__ __forceinline__ void gemm_load_stage(uint sbase, int buf, int m0c, int n0c,
                                                int k0, int t)
{
    uint aHi = sbase + (uint)buf * STAGE_BYTES;
    uint aLo = aHi + A_ELEMS * 2;
    uint bHi = aLo + A_ELEMS * 2;
    uint bLo = bHi + B_ELEMS * 2;
    #pragma unroll
    for (int i = 0; i < 4; i++) {                 // A: 128 rows x 8 chunks
        int id = t + 256 * i;
        int row = id >> 3, c = id & 7;
        uint off = (uint)(row * AROW + c * 8) * 2;
        CP16(aHi + off, &g_Ahi[m0c + row][k0 + c * 8]);
        CP16(aLo + off, &g_Alo[m0c + row][k0 + c * 8]);
    }
    #pragma unroll
    for (int i = 0; i < 4; i++) {                 // B: 64 rows x 16 chunks
        int id = t + 256 * i;
        int row = id >> 4, c = id & 15;
        uint off = (uint)(row * BROW + c * 8) * 2;
        CP16(bHi + off, &g_Bhi[k0 + row][n0c + c * 8]);
        CP16(bLo + off, &g_Blo[k0 + row][n0c + c * 8]);
    }
}

__global__ void __launch_bounds__(256, 1) k_gemm()
{
    uint sbase = (uint)__cvta_generic_to_shared(smem_g);

    int n0c = blockIdx.x * 128;
    int m0c = blockIdx.y * 128;
    int kz  = blockIdx.z;

    int t = threadIdx.x;
    int lane = t & 31, w = t >> 5;
    int wm = w & 3, wn = w >> 2;        // warp tile: rows [wm*32,+32), cols [wn*64,+64)

    float acc[2][8][4];
    #pragma unroll
    for (int i = 0; i < 2; i++)
        #pragma unroll
        for (int j = 0; j < 8; j++)
            #pragma unroll
            for (int e = 0; e < 4; e++) acc[i][j][e] = 0.f;

    // precomputed ldmatrix lane addresses (offsets within stage)
    int arow = wm * 32 + (lane & 15);
    int acol = ((lane >> 4) & 1) * 8;
    uint a_off = (uint)(arow * AROW + acol) * 2;
    int bkr = lane & 15;
    int bnc = wn * 64 + ((lane >> 4) & 1) * 8;
    uint b_off = (uint)(bkr * BROW + bnc) * 2;

    int kbase = kz * (NSTEP * 64);

    // prologue: stages 0 and 1 in flight
    gemm_load_stage(sbase, 0, m0c, n0c, kbase, t);
    CP_COMMIT();
    gemm_load_stage(sbase, 1, m0c, n0c, kbase + 64, t);
    CP_COMMIT();

    for (int s = 0; s < NSTEP; s++) {
        CP_WAIT_G1();          // stage s resident (at most stage s+1 pending)
        __syncthreads();       // all warps past compute(s-1); buffer (s+2)%3 free

        if (s + 2 < NSTEP) {   // prefetch stage s+2 (overlaps with compute(s))
            gemm_load_stage(sbase, (s + 2) % NSTAGE, m0c, n0c, kbase + (s + 2) * 64, t);
            CP_COMMIT();
        }

        uint aHi = sbase + (uint)(s % NSTAGE) * STAGE_BYTES;
        uint aLo = aHi + A_ELEMS * 2;
        uint bHi = aLo + A_ELEMS * 2;
        uint bLo = bHi + B_ELEMS * 2;

        #pragma unroll
        for (int ks = 0; ks < 4; ks++) {
            uint ah[2][4], al[2][4];
            #pragma unroll
            for (int i = 0; i < 2; i++) {
                LDSM_X4(ah[i], aHi + a_off + (uint)(i * 16 * AROW + ks * 16) * 2);
                LDSM_X4(al[i], aLo + a_off + (uint)(i * 16 * AROW + ks * 16) * 2);
            }
            uint bh[4][4], bl[4][4];
            #pragma unroll
            for (int j2 = 0; j2 < 4; j2++) {
                LDSM_X4_T(bh[j2], bHi + b_off + (uint)(ks * 16 * BROW + j2 * 16) * 2);
                LDSM_X4_T(bl[j2], bLo + b_off + (uint)(ks * 16 * BROW + j2 * 16) * 2);
            }
            #pragma unroll
            for (int i = 0; i < 2; i++)
                #pragma unroll
                for (int j2 = 0; j2 < 4; j2++)
                    #pragma unroll
                    for (int h = 0; h < 2; h++) {
                        int j = j2 * 2 + h;
                        MMA16816(acc[i][j], ah[i], bh[j2][2*h], bh[j2][2*h+1]);
                        MMA16816(acc[i][j], ah[i], bl[j2][2*h], bl[j2][2*h+1]);
                        MMA16816(acc[i][j], al[i], bh[j2][2*h], bh[j2][2*h+1]);
                    }
        }
    }

    // epilogue: split-K partials
    int g = lane >> 2, tig = lane & 3;
    #pragma unroll
    for (int i = 0; i < 2; i++) {
        int r = m0c + wm * 32 + i * 16 + g;
        #pragma unroll
        for (int j = 0; j < 8; j++) {
            int col = n0c + wn * 64 + j * 8 + tig * 2;
            *(float2*)&g_part[kz][r    ][col] = make_float2(acc[i][j][0], acc[i][j][1]);
            *(float2*)&g_part[kz][r + 8][col] = make_float2(acc[i][j][2], acc[i][j][3]);
        }
    }
}

// ---------------- Kernel 5: fused reduce + decoder tail --------------------
__global__ void k_tail(const float* __restrict__ bd1,
                       const float* __restrict__ Wd2,
                       const float* __restrict__ bd2,
                       float* __restrict__ out)
{
    int b = blockIdx.x;           // 256 blocks, 256 threads
    int n = threadIdx.x;
    __shared__ float h[256];
    __shared__ float red[4][64];

    float s = 0.f;
    #pragma unroll
    for (int z = 0; z < 32; z++) s += g_part[z][b][n];
    h[n] = fmaxf(s + bd1[n], 0.f);
    __syncthreads();

    int n2 = n & 63, q = n >> 6;
    float s2 = 0.f;
    #pragma unroll 8
    for (int j = q * 64; j < q * 64 + 64; j++) s2 += h[j] * Wd2[j * 64 + n2];
    red[q][n2] = s2;
    __syncthreads();

    if (n < 64)
        out[b * 64 + n] = fmaxf(red[0][n] + red[1][n] + red[2][n] + red[3][n] + bd2[n], 0.f);
}

// ---------------------------------------------------------------------------
extern "C" void kernel_launch(void* const* d_in, const int* in_sizes, int n_in,
                              void* d_out, int out_size)
{
    const float* x       = (const float*)d_in[0];
    const float* W1      = (const float*)d_in[1];
    const float* b1      = (const float*)d_in[2];
    const float* W2      = (const float*)d_in[3];
    const float* b2      = (const float*)d_in[4];
    const float* scaling = (const float*)d_in[5];
    const float* Wd1     = (const float*)d_in[6];
    const float* bd1     = (const float*)d_in[7];
    const float* Wd2     = (const float*)d_in[8];
    const float* bd2     = (const float*)d_in[9];
    float* out = (float*)d_out;

    int smem_bytes = NSTAGE * STAGE_BYTES;   // 215040
    cudaFuncSetAttribute(k_gemm, cudaFuncAttributeMaxDynamicSharedMemorySize, smem_bytes);

    k_prep<<<16384, 256>>>(Wd1);
    k_encoder<<<NB, 128>>>(x, W1, b1, W2, b2, scaling);
    k_wv<<<NB, 256>>>();
    k_probs<<<dim3(NB, 4), 256>>>();
    k_gemm<<<dim3(2, 2, 32), 256, smem_bytes>>>();
    k_tail<<<NB, 256>>>(bd1, Wd2, bd2, out);
}